// round 12
// baseline (speedup 1.0000x reference)
#include <cuda_runtime.h>
#include <cstdint>

#define LV    17
#define NLUT  83521   // 17^4

// 1.34 MB precomputed LUT: final (rounded, clipped, permuted) 4x4 tile per
// index, stored as int8 (exact: values are integers in [-128,127]).
// Entry idx*4 + row = one packed row (4 x int8) of the tile.
__device__ int g_lut8[NLUT * 4];

__device__ __forceinline__ int C2i(int n){ return n*(n-1)/2; }
__device__ __forceinline__ int C3i(int n){ return n*(n-1)*(n-2)/6; }
__device__ __forceinline__ int C4i(int n){ return n*(n-1)*(n-2)*(n-3)/24; }

// One thread per possible index value: full symmetry math, done once per call.
__global__ void build_lut(const float* __restrict__ w0,
                          const float* __restrict__ w1,
                          const float* __restrict__ w2)
{
    int idx = blockIdx.x * blockDim.x + threadIdx.x;
    if (idx >= NLUT) return;

    int t  = idx;
    int d  = t % LV; t /= LV;
    int c  = t % LV; t /= LV;
    int b  = t % LV;
    int a  = t / LV;

    // ranks = argsort(argsort(vals)), stable ties via pairwise counting.
    int r0 = 0, r1 = 0, r2 = 0, r3 = 0;
    if (a <= b) r1++; else r0++;
    if (a <= c) r2++; else r0++;
    if (a <= d) r3++; else r0++;
    if (b <= c) r2++; else r1++;
    if (b <= d) r3++; else r1++;
    if (c <= d) r3++; else r2++;

    // sorted values: sv[rank[i]] = v[i]
    int sv[4];
    sv[r0] = a; sv[r1] = b; sv[r2] = c; sv[r3] = d;
    int sa = sv[0], sb = sv[1], sc = sv[2], sd = sv[3];

    // multiset rank (lexicographic position among nondecreasing 4-tuples);
    // validated at (0,0,0,0)->0, (0,0,1,1)->17, (0,1,1,1)->153, (1,1,1,1)->969.
    int widx = (C4i(LV+3) - C4i(LV - sa + 3))
             + (C3i(LV - sa + 2) - C3i(LV - sb + 2))
             + (C2i(LV - sb + 1) - C2i(LV - sc + 1))
             + (sd - sc);

    // (type, rot, flip): replicate the reference's symmetry-map construction
    // verbatim.  np.rot90 on 2x2 (flat row-major): [a,b,c,d] -> [b,d,a,c].
    // Column flip p[:, ::-1]:                      [a,b,c,d] -> [b,a,d,c].
    // The 24 generated permutations are disjoint and cover all of S4.
    int ptype = 2, rot = 0, flip = 0;
    {
        const int pats[3][4] = { {0,1,2,3}, {0,1,3,2}, {0,2,3,1} };
        #pragma unroll
        for (int pt = 0; pt < 3; pt++) {
            int p0 = pats[pt][0], p1 = pats[pt][1], p2 = pats[pt][2], p3 = pats[pt][3];
            #pragma unroll
            for (int f = 0; f < 2; f++) {
                int q0 = p0, q1 = p1, q2 = p2, q3 = p3;
                #pragma unroll
                for (int rk = 0; rk < 4; rk++) {
                    if (q0 == r0 && q1 == r1 && q2 == r2 && q3 == r3) {
                        ptype = pt; rot = rk; flip = f;
                    }
                    int n0 = q1, n1 = q3, n2 = q0, n3 = q2;   // rot90 (CCW)
                    q0 = n0; q1 = n1; q2 = n2; q3 = n3;
                }
                int s0 = p1, s1 = p0, s2 = p3, s3 = p2;       // p = p[:, ::-1]
                p0 = s0; p1 = s1; p2 = s2; p3 = s3;
            }
        }
    }

    const float* w = (ptype == 0 ? w0 : (ptype == 1 ? w1 : w2)) + (size_t)widx * 16;
    float m[16];
    #pragma unroll
    for (int i = 0; i < 16; i++) m[i] = w[i];

    // Tile transform, derivation-free: build the source-index map T(p) = m[mi[p]]
    // by composing the reference's ops in its exact order:
    //   1) flip:  out = out[:, :, :, ::-1]   i.e. new(i,j) = cur(i, 3-j)
    //   2) rot90 applied 'rot' times (CCW):  new(i,j) = cur(j, 3-i)
    int mi[16];
    #pragma unroll
    for (int p = 0; p < 16; p++) mi[p] = p;
    if (flip) {
        int tmp[16];
        #pragma unroll
        for (int i = 0; i < 4; i++)
            #pragma unroll
            for (int j = 0; j < 4; j++)
                tmp[i*4 + j] = mi[i*4 + (3 - j)];
        #pragma unroll
        for (int p = 0; p < 16; p++) mi[p] = tmp[p];
    }
    for (int k = 0; k < rot; k++) {
        int tmp[16];
        #pragma unroll
        for (int i = 0; i < 4; i++)
            #pragma unroll
            for (int j = 0; j < 4; j++)
                tmp[i*4 + j] = mi[j*4 + (3 - i)];
        #pragma unroll
        for (int p = 0; p < 16; p++) mi[p] = tmp[p];
    }

    #pragma unroll
    for (int row = 0; row < 4; row++) {
        unsigned int packed = 0;
        #pragma unroll
        for (int col = 0; col < 4; col++) {
            float val = rintf(m[mi[row*4 + col]]);   // round half-to-even == jnp.round
            val = fminf(fmaxf(val, -128.0f), 127.0f);
            int q = (int)val;                         // exact integer in [-128,127]
            packed |= ((unsigned int)q & 0xFFu) << (col * 8);
        }
        g_lut8[idx * 4 + row] = (int)packed;
    }
}

// Pure gather, 4 lanes per element: thread g handles element g>>2, row g&3.
// Lane loads one packed int32 (4 x int8), expands to float4, stores 16B.
// -> warp stores one contiguous 512B span per STG.128 (perfect coalescing);
//    LUT reads are 16B/tile from a 1.34MB table (L2-resident, partly L1-hit).
__global__ void __launch_bounds__(512)
gather_out(const int* __restrict__ index, float4* __restrict__ out, int n4)
{
    int g = blockIdx.x * blockDim.x + threadIdx.x;
    if (g >= n4) return;

    int e = g >> 2;
    int p = g & 3;
    int idx = __ldcs(index + e);                 // 4 lanes same addr -> broadcast
    int v = __ldg(&g_lut8[idx * 4 + p]);         // read-only path; keep LUT hot

    float4 o;
    o.x = (float)((v << 24) >> 24);              // sign-extend byte 0..3
    o.y = (float)((v << 16) >> 24);
    o.z = (float)((v <<  8) >> 24);
    o.w = (float)( v        >> 24);
    __stcs(out + g, o);                          // streaming store: evict-first
}

extern "C" void kernel_launch(void* const* d_in, const int* in_sizes, int n_in,
                              void* d_out, int out_size)
{
    const int*   index = (const int*)  d_in[0];
    const float* w0    = (const float*)d_in[1];
    const float* w1    = (const float*)d_in[2];
    const float* w2    = (const float*)d_in[3];
    int n  = in_sizes[0];
    int n4 = n * 4;

    build_lut<<<(NLUT + 255) / 256, 256>>>(w0, w1, w2);
    gather_out<<<(n4 + 511) / 512, 512>>>(index, (float4*)d_out, n4);
}

// round 14
// speedup vs baseline: 1.2003x; 1.2003x over previous
#include <cuda_runtime.h>
#include <cstdint>

#define LV    17
#define NLUT  83521   // 17^4

// 1.34 MB precomputed LUT: final (rounded, clipped, permuted) 4x4 tile per
// index, stored as int8 (exact: values are integers in [-128,127]).
// Entry idx*4 + row = one packed row (4 x int8) of the tile.
__device__ int g_lut8[NLUT * 4];

__device__ __forceinline__ int C2i(int n){ return n*(n-1)/2; }
__device__ __forceinline__ int C3i(int n){ return n*(n-1)*(n-2)/6; }
__device__ __forceinline__ int C4i(int n){ return n*(n-1)*(n-2)*(n-3)/24; }

// One thread per possible index value: full symmetry math, done once per call.
// All arrays register-resident: sorting network for sorted values, fully
// unrolled predicated composition for the permutation map, and the final
// permuted read goes straight to global (no runtime-indexed local array).
__global__ void build_lut(const float* __restrict__ w0,
                          const float* __restrict__ w1,
                          const float* __restrict__ w2)
{
    int idx = blockIdx.x * blockDim.x + threadIdx.x;
    if (idx >= NLUT) return;

    int t  = idx;
    int d  = t % LV; t /= LV;
    int c  = t % LV; t /= LV;
    int b  = t % LV;
    int a  = t / LV;

    // ranks = argsort(argsort(vals)), stable ties via pairwise counting.
    int r0 = 0, r1 = 0, r2 = 0, r3 = 0;
    if (a <= b) r1++; else r0++;
    if (a <= c) r2++; else r0++;
    if (a <= d) r3++; else r0++;
    if (b <= c) r2++; else r1++;
    if (b <= d) r3++; else r1++;
    if (c <= d) r3++; else r2++;

    // sorted values via register-only sorting network (no dynamic indexing).
    int lo1 = min(a, b), hi1 = max(a, b);
    int lo2 = min(c, d), hi2 = max(c, d);
    int sa = min(lo1, lo2);
    int sd = max(hi1, hi2);
    int m1 = max(lo1, lo2), m2 = min(hi1, hi2);
    int sb = min(m1, m2);
    int sc = max(m1, m2);

    // multiset rank (lexicographic position among nondecreasing 4-tuples);
    // validated at (0,0,0,0)->0, (0,0,1,1)->17, (0,1,1,1)->153, (1,1,1,1)->969.
    int widx = (C4i(LV+3) - C4i(LV - sa + 3))
             + (C3i(LV - sa + 2) - C3i(LV - sb + 2))
             + (C2i(LV - sb + 1) - C2i(LV - sc + 1))
             + (sd - sc);

    // (type, rot, flip): replicate the reference's symmetry-map construction
    // verbatim.  np.rot90 on 2x2 (flat row-major): [a,b,c,d] -> [b,d,a,c].
    // Column flip p[:, ::-1]:                      [a,b,c,d] -> [b,a,d,c].
    // The 24 generated permutations are disjoint and cover all of S4.
    int ptype = 2, rot = 0, flip = 0;
    {
        const int pats[3][4] = { {0,1,2,3}, {0,1,3,2}, {0,2,3,1} };
        #pragma unroll
        for (int pt = 0; pt < 3; pt++) {
            int p0 = pats[pt][0], p1 = pats[pt][1], p2 = pats[pt][2], p3 = pats[pt][3];
            #pragma unroll
            for (int f = 0; f < 2; f++) {
                int q0 = p0, q1 = p1, q2 = p2, q3 = p3;
                #pragma unroll
                for (int rk = 0; rk < 4; rk++) {
                    if (q0 == r0 && q1 == r1 && q2 == r2 && q3 == r3) {
                        ptype = pt; rot = rk; flip = f;
                    }
                    int n0 = q1, n1 = q3, n2 = q0, n3 = q2;   // rot90 (CCW)
                    q0 = n0; q1 = n1; q2 = n2; q3 = n3;
                }
                int s0 = p1, s1 = p0, s2 = p3, s3 = p2;       // p = p[:, ::-1]
                p0 = s0; p1 = s1; p2 = s2; p3 = s3;
            }
        }
    }

    // Tile transform: source-index map T(p) = w[mi[p]], composed in the
    // reference's exact op order (flip first, then rot90 x rot). All steps
    // fully unrolled with compile-time indices -> mi[] lives in registers
    // (predicated selects), no local-memory spills.
    int mi[16];
    #pragma unroll
    for (int p = 0; p < 16; p++) mi[p] = p;
    {
        // flip: new(i,j) = cur(i, 3-j)
        int tmp[16];
        #pragma unroll
        for (int i = 0; i < 4; i++)
            #pragma unroll
            for (int j = 0; j < 4; j++)
                tmp[i*4 + j] = mi[i*4 + (3 - j)];
        #pragma unroll
        for (int p = 0; p < 16; p++) mi[p] = flip ? tmp[p] : mi[p];
    }
    #pragma unroll
    for (int k = 0; k < 3; k++) {
        // rot90 (CCW): new(i,j) = cur(j, 3-i); applied while k < rot.
        bool doit = (k < rot);
        int tmp[16];
        #pragma unroll
        for (int i = 0; i < 4; i++)
            #pragma unroll
            for (int j = 0; j < 4; j++)
                tmp[i*4 + j] = mi[j*4 + (3 - i)];
        #pragma unroll
        for (int p = 0; p < 16; p++) mi[p] = doit ? tmp[p] : mi[p];
    }

    const float* w = (ptype == 0 ? w0 : (ptype == 1 ? w1 : w2)) + (size_t)widx * 16;

    #pragma unroll
    for (int row = 0; row < 4; row++) {
        unsigned int packed = 0;
        #pragma unroll
        for (int col = 0; col < 4; col++) {
            // mi[const] is a register; load the permuted source directly.
            float val = __ldg(w + mi[row*4 + col]);
            val = rintf(val);                        // round half-to-even == jnp.round
            val = fminf(fmaxf(val, -128.0f), 127.0f);
            int q = (int)val;                         // exact integer in [-128,127]
            packed |= ((unsigned int)q & 0xFFu) << (col * 8);
        }
        g_lut8[idx * 4 + row] = (int)packed;
    }
}

// Gather, 2 independent elements per thread (e and e+n/2) for 2x memory-level
// parallelism: the Round-12 profile showed no unit saturated (L1 54%, L2 45%,
// DRAM 29%, issue 20%) -> latency-bound on the single outstanding scattered
// LUT load per warp. Both store spans stay warp-contiguous 512B.
__global__ void __launch_bounds__(512)
gather_out(const int* __restrict__ index, float4* __restrict__ out,
           int half_elems, int half4)
{
    int g = blockIdx.x * blockDim.x + threadIdx.x;
    if (g >= half4) return;

    int e1 = g >> 2;
    int p  = g & 3;
    int e2 = e1 + half_elems;

    int i1 = __ldcs(index + e1);                 // 4 lanes same addr -> broadcast
    int i2 = __ldcs(index + e2);
    int v1 = __ldg(&g_lut8[i1 * 4 + p]);         // two independent scattered loads
    int v2 = __ldg(&g_lut8[i2 * 4 + p]);         //   in flight per thread

    float4 o1, o2;
    o1.x = (float)((v1 << 24) >> 24);            // sign-extend bytes 0..3
    o1.y = (float)((v1 << 16) >> 24);
    o1.z = (float)((v1 <<  8) >> 24);
    o1.w = (float)( v1        >> 24);
    o2.x = (float)((v2 << 24) >> 24);
    o2.y = (float)((v2 << 16) >> 24);
    o2.z = (float)((v2 <<  8) >> 24);
    o2.w = (float)( v2        >> 24);

    __stcs(out + g,         o1);                 // streaming stores: evict-first
    __stcs(out + g + half4, o2);
}

extern "C" void kernel_launch(void* const* d_in, const int* in_sizes, int n_in,
                              void* d_out, int out_size)
{
    const int*   index = (const int*)  d_in[0];
    const float* w0    = (const float*)d_in[1];
    const float* w1    = (const float*)d_in[2];
    const float* w2    = (const float*)d_in[3];
    int n          = in_sizes[0];        // 2097152 (even)
    int half_elems = n >> 1;
    int half4      = half_elems * 4;     // threads = n*4/2

    build_lut<<<(NLUT + 255) / 256, 256>>>(w0, w1, w2);
    gather_out<<<(half4 + 511) / 512, 512>>>(index, (float4*)d_out,
                                             half_elems, half4);
}